// round 5
// baseline (speedup 1.0000x reference)
#include <cuda_runtime.h>
#include <cuda_bf16.h>
#include <cuda_fp8.h>

#define NPTS     163840
#define KNEI     8
#define FDIM     32
#define HDIM     256
#define EPSV     1e-8f
#define MTILE    128
#define NTHREADS 512
#define APB      272         // act pitch bytes (fp8): 68 words = 4 mod 32 -> conflict-free ldmatrix
#define WPB      144         // weight pitch bytes: 36 words = 4 mod 32

// smem layout (bytes)
#define SM_ACT   0                        // [128][APB] fp8 = 34,816
#define SM_WB    34816                    // 2 x [256][WPB] = 2 x 36,864
#define SM_BS    (SM_WB + 73728)          // 4 x 256 floats
#define SM_HD    (SM_BS + 4096)           // head weights 256 + 840 floats
#define SMEM_BYTES (SM_HD + 4384)

// -------- device scratch (fp8 payloads) --------
__device__ unsigned char g_feat[(size_t)NPTS * FDIM];   // e4m3(feat * 2^4)
__device__ unsigned char g_w1a[HDIM * FDIM];            // e4m3(W^T * 2^8)
__device__ unsigned char g_w1b[HDIM * HDIM];
__device__ unsigned char g_w3a[HDIM * HDIM];
__device__ unsigned char g_w3b[HDIM * HDIM];

__device__ __forceinline__ unsigned smem_u32(const void* p) {
    unsigned a;
    asm("{ .reg .u64 t; cvta.to.shared.u64 t, %1; cvt.u32.u64 %0, t; }" : "=r"(a) : "l"(p));
    return a;
}
__device__ __forceinline__ void ldsm4(unsigned& r0, unsigned& r1, unsigned& r2,
                                      unsigned& r3, unsigned addr) {
    asm volatile("ldmatrix.sync.aligned.m8n8.x4.shared.b16 {%0,%1,%2,%3}, [%4];"
                 : "=r"(r0), "=r"(r1), "=r"(r2), "=r"(r3) : "r"(addr));
}
__device__ __forceinline__ void cp16(unsigned dst, const void* src) {
    asm volatile("cp.async.cg.shared.global [%0], [%1], 16;" :: "r"(dst), "l"(src) : "memory");
}
#define CP_COMMIT() asm volatile("cp.async.commit_group;" ::: "memory")
__device__ __forceinline__ unsigned short fp8x2(float hi, float lo) {
    unsigned short v;
    asm("cvt.rn.satfinite.e4m3x2.f32 %0, %1, %2;" : "=h"(v) : "f"(hi), "f"(lo));
    return v;
}
__device__ __forceinline__ float fp8tof(unsigned char b) {
    __nv_fp8_e4m3 t; t.__x = b;
    return float(t);
}

// ============================================================
// Kernel 1: W^T, quantize to e4m3 * 2^8
// ============================================================
__global__ void convert_weights_kernel(const float* __restrict__ W1a,
                                       const float* __restrict__ W1b,
                                       const float* __restrict__ W3a,
                                       const float* __restrict__ W3b) {
    int idx = blockIdx.x * blockDim.x + threadIdx.x;
    if (idx < HDIM * FDIM) {
        int o = idx / FDIM, i = idx - o * FDIM;
        g_w1a[idx] = (unsigned char)fp8x2(0.f, W1a[i * HDIM + o] * 256.f);
    }
    if (idx < HDIM * HDIM) {
        int o = idx / HDIM, i = idx - o * HDIM;
        g_w1b[idx] = (unsigned char)fp8x2(0.f, W1b[i * HDIM + o] * 256.f);
        g_w3a[idx] = (unsigned char)fp8x2(0.f, W3a[i * HDIM + o] * 256.f);
        g_w3b[idx] = (unsigned char)fp8x2(0.f, W3b[i * HDIM + o] * 256.f);
    }
}

// ============================================================
// Kernel 2: aggregation -> e4m3(feat * 2^4)
// ============================================================
__global__ void prep_kernel(const float* __restrict__ emb,
                            const float* __restrict__ dists,
                            const int*   __restrict__ mask) {
    int gw   = (blockIdx.x * blockDim.x + threadIdx.x) >> 5;
    int lane = threadIdx.x & 31;
    if (gw >= NPTS) return;

    float w = 0.f;
    if (lane < KNEI) {
        const float* d = dists + (size_t)gw * (KNEI * 3) + lane * 3;
        float d0 = d[0], d1 = d[1], d2 = d[2];
        float n2 = d0 * d0 + d1 * d1 + d2 * d2;
        w = mask[(size_t)gw * KNEI + lane] ? (1.0f / fmaxf(n2, EPSV)) : 0.f;
    }
    float ws = w;
    #pragma unroll
    for (int o = 16; o > 0; o >>= 1) ws += __shfl_xor_sync(0xffffffffu, ws, o);
    w /= fmaxf(ws, EPSV);

    const float* e = emb + (size_t)gw * (KNEI * FDIM) + lane;
    float acc = 0.f;
    #pragma unroll
    for (int k = 0; k < KNEI; k++) {
        float wk = __shfl_sync(0xffffffffu, w, k);
        acc += wk * e[k * FDIM];
    }
    g_feat[(size_t)gw * FDIM + lane] = (unsigned char)fp8x2(0.f, acc * 16.f);
}

// ncu-alignment no-op (shifts mlp_kernel to global launch index 5)
__global__ void noop_kernel() {}

// stage one k-chunk of W^T[256][Kbytes] rows into [256][WPB] buffer
__device__ __forceinline__ void stage_chunk(unsigned dst, const unsigned char* __restrict__ gW,
                                            int slog, int Kbytes, int coff, int tid) {
    int total = 256 << slog;
    for (int i = tid; i < total; i += NTHREADS) {
        int r = i >> slog, s = i & ((1 << slog) - 1);
        cp16(dst + r * WPB + s * 16, gW + (size_t)r * Kbytes + coff + s * 16);
    }
}

// ============================================================
// Kernel 3: fused fp8 MLP + heads. 128 rows/CTA, 16 warps 4x4.
// ============================================================
__global__ void __launch_bounds__(NTHREADS, 1)
mlp_kernel(const float* __restrict__ b1a, const float* __restrict__ b1b,
           const float* __restrict__ b3a, const float* __restrict__ b3b,
           const float* __restrict__ Wa,  const float* __restrict__ ba,
           const float* __restrict__ Wc,  const float* __restrict__ bc,
           const float* __restrict__ viewdirs, float* __restrict__ out)
{
    extern __shared__ char smem[];
    unsigned sb = smem_u32(smem);
    int tid = threadIdx.x, lane = tid & 31, wid = tid >> 5;
    int wm = wid >> 2, wn = wid & 3;
    int row0 = blockIdx.x * MTILE;

    // ---- initial staging: feat tile + L1 weight chunk (group 0) ----
    if (tid < 256) {   // feat: 128 rows x 32B
        int r = tid >> 1, s = tid & 1;
        cp16(sb + SM_ACT + r * APB + s * 16,
             g_feat + (size_t)(row0 + r) * FDIM + s * 16);
    }
    stage_chunk(sb + SM_WB, g_w1a, 1, FDIM, 0, tid);
    CP_COMMIT();
    if (tid < 256) {
        float* bs = (float*)(smem + SM_BS);
        bs[tid] = b1a[tid]; bs[256 + tid] = b1b[tid];
        bs[512 + tid] = b3a[tid]; bs[768 + tid] = b3b[tid];
        ((float*)(smem + SM_HD))[tid] = Wa[tid];
    }
    for (int i = tid; i < 840; i += NTHREADS)
        ((float*)(smem + SM_HD))[256 + i] = Wc[i];

    // ldmatrix pre-offsets (identical shape to bf16 version; fp8 via b16 ldsm)
    const int mrow = (lane >> 3) & 1, mcol = lane >> 4, i8 = lane & 7;
    unsigned preA[2], preBr[4];
    #pragma unroll
    for (int mt = 0; mt < 2; mt++) {
        int r = wm * 32 + mt * 16 + mrow * 8 + i8;
        preA[mt] = sb + SM_ACT + r * APB + mcol * 16;
    }
    #pragma unroll
    for (int p = 0; p < 4; p++) {
        int n = wn * 64 + p * 16 + mcol * 8 + i8;
        preBr[p] = n * WPB + mrow * 16;
    }
    const int g8 = lane >> 2, tq = lane & 3;

    const float dsc[4] = { 1.f/4096.f, 1.f/16384.f, 1.f/65536.f, 1.f/131072.f };
    const float osc[4] = { 64.f, 256.f, 512.f, 1024.f };

    int g = 0;
    #pragma unroll 1
    for (int L = 0; L < 4; L++) {
        int chunks = (L == 0) ? 1 : 2;
        int ktiles = (L == 0) ? 1 : 4;
        float acc[2][8][4];
        #pragma unroll
        for (int mt = 0; mt < 2; mt++)
            #pragma unroll
            for (int nt = 0; nt < 8; nt++)
                #pragma unroll
                for (int q = 0; q < 4; q++) acc[mt][nt][q] = 0.f;

        #pragma unroll 1
        for (int c = 0; c < chunks; c++, g++) {
            int nxt = g + 1;
            if (nxt <= 6) {
                const unsigned char* wp; int nc;
                if (nxt <= 2)      { wp = g_w1b; nc = nxt - 1; }
                else if (nxt <= 4) { wp = g_w3a; nc = nxt - 3; }
                else               { wp = g_w3b; nc = nxt - 5; }
                stage_chunk(sb + SM_WB + (nxt & 1) * (256 * WPB), wp, 3, HDIM, nc * 128, tid);
                CP_COMMIT();
                asm volatile("cp.async.wait_group 1;" ::: "memory");
            } else {
                asm volatile("cp.async.wait_group 0;" ::: "memory");
            }
            __syncthreads();

            unsigned wb = sb + SM_WB + (g & 1) * (256 * WPB);
            int abase = (L == 0) ? 0 : c * 128;
            #pragma unroll
            for (int kt = 0; kt < 4; kt++) {
                if (kt >= ktiles) break;
                unsigned ka = abase + kt * 32, kw = kt * 32;
                unsigned a[2][4], b[8][2];
                ldsm4(a[0][0], a[0][1], a[0][2], a[0][3], preA[0] + ka);
                ldsm4(a[1][0], a[1][1], a[1][2], a[1][3], preA[1] + ka);
                ldsm4(b[0][0], b[0][1], b[1][0], b[1][1], wb + preBr[0] + kw);
                ldsm4(b[2][0], b[2][1], b[3][0], b[3][1], wb + preBr[1] + kw);
                ldsm4(b[4][0], b[4][1], b[5][0], b[5][1], wb + preBr[2] + kw);
                ldsm4(b[6][0], b[6][1], b[7][0], b[7][1], wb + preBr[3] + kw);
                #pragma unroll
                for (int mt = 0; mt < 2; mt++)
                    #pragma unroll
                    for (int nt = 0; nt < 8; nt++)
                        asm volatile(
                            "mma.sync.aligned.m16n8k32.row.col.f32.e4m3.e4m3.f32 "
                            "{%0,%1,%2,%3}, {%4,%5,%6,%7}, {%8,%9}, {%0,%1,%2,%3};\n"
                            : "+f"(acc[mt][nt][0]), "+f"(acc[mt][nt][1]),
                              "+f"(acc[mt][nt][2]), "+f"(acc[mt][nt][3])
                            : "r"(a[mt][0]), "r"(a[mt][1]), "r"(a[mt][2]), "r"(a[mt][3]),
                              "r"(b[nt][0]), "r"(b[nt][1]));
            }
        }
        __syncthreads();   // all mma reads of act done before in-place epilogue

        const float* bs = (const float*)(smem + SM_BS) + L * 256;
        float ds = dsc[L], os = osc[L];
        #pragma unroll
        for (int mt = 0; mt < 2; mt++) {
            int r = wm * 32 + mt * 16 + g8;
            #pragma unroll
            for (int nt = 0; nt < 8; nt++) {
                int col = wn * 64 + nt * 8 + tq * 2;
                float bz0 = bs[col], bz1 = bs[col + 1];
                float v0 = fmaxf(acc[mt][nt][0] * ds + bz0, 0.f) * os;
                float v1 = fmaxf(acc[mt][nt][1] * ds + bz1, 0.f) * os;
                float v2 = fmaxf(acc[mt][nt][2] * ds + bz0, 0.f) * os;
                float v3 = fmaxf(acc[mt][nt][3] * ds + bz1, 0.f) * os;
                *(unsigned short*)(smem + SM_ACT + r * APB + col)       = fp8x2(v1, v0);
                *(unsigned short*)(smem + SM_ACT + (r + 8) * APB + col) = fp8x2(v3, v2);
            }
        }
    }
    __syncthreads();

    // ---- heads: alpha (256->1) + color (280->3); h stored as e4m3(h*2^10) ----
    int r = tid >> 1, t = tid & 1;
    if (r < MTILE) {
        const unsigned char* ar = (const unsigned char*)(smem + SM_ACT) + r * APB;
        const float* hWa = (const float*)(smem + SM_HD);
        const float* hWc = hWa + 256;                    // [280][3]
        float sa = 0.f, c0 = 0.f, c1 = 0.f, c2 = 0.f;
        for (int k = t * 128; k < t * 128 + 128; k++) {
            float h = fp8tof(ar[k]);
            sa += h * hWa[k];
            c0 += h * hWc[k * 3 + 0];
            c1 += h * hWc[k * 3 + 1];
            c2 += h * hWc[k * 3 + 2];
        }
        const float hs = 1.f / 1024.f;
        sa *= hs; c0 *= hs; c1 *= hs; c2 *= hs;
        if (t == 0) {   // viewdir PE, exact fp32
            const float* v = viewdirs + (size_t)(row0 + r) * 3;
            float vx = v[0], vy = v[1], vz = v[2];
            float inv = 1.f / fmaxf(sqrtf(vx * vx + vy * vy + vz * vz), EPSV);
            vx *= inv; vy *= inv; vz *= inv;
            #pragma unroll
            for (int i = 0; i < 4; i++) {
                float f = (float)(1 << i);
                float pe[6];
                pe[0] = sinf(vx * f); pe[1] = sinf(vy * f); pe[2] = sinf(vz * f);
                pe[3] = cosf(vx * f); pe[4] = cosf(vy * f); pe[5] = cosf(vz * f);
                #pragma unroll
                for (int j = 0; j < 6; j++) {
                    const float* wr = hWc + (HDIM + i * 6 + j) * 3;
                    c0 += pe[j] * wr[0]; c1 += pe[j] * wr[1]; c2 += pe[j] * wr[2];
                }
            }
        }
        sa += __shfl_xor_sync(0xffffffffu, sa, 1);
        c0 += __shfl_xor_sync(0xffffffffu, c0, 1);
        c1 += __shfl_xor_sync(0xffffffffu, c1, 1);
        c2 += __shfl_xor_sync(0xffffffffu, c2, 1);
        if (t == 0) {
            float apre  = sa + ba[0] - 1.0f;
            float alpha = (apre > 20.f) ? apre : log1pf(expf(apre));
            float r0 = c0 + bc[0], r1 = c1 + bc[1], r2 = c2 + bc[2];
            const float sc = 1.0f + 2e-3f, sh = 1e-3f;
            float4 o4;
            o4.x = alpha;
            o4.y = sc / (1.f + expf(-r0)) - sh;
            o4.z = sc / (1.f + expf(-r1)) - sh;
            o4.w = sc / (1.f + expf(-r2)) - sh;
            *(float4*)(out + (size_t)(row0 + r) * 4) = o4;
        }
    }
}

// ============================================================
extern "C" void kernel_launch(void* const* d_in, const int* in_sizes, int n_in,
                              void* d_out, int out_size) {
    const float* emb   = (const float*)d_in[0];
    const float* dists = (const float*)d_in[1];
    const float* vdirs = (const float*)d_in[2];
    const int*   mask  = (const int*)d_in[3];
    const float* W1a = (const float*)d_in[4];
    const float* b1a = (const float*)d_in[5];
    const float* W1b = (const float*)d_in[6];
    const float* b1b = (const float*)d_in[7];
    const float* W3a = (const float*)d_in[8];
    const float* b3a = (const float*)d_in[9];
    const float* W3b = (const float*)d_in[10];
    const float* b3b = (const float*)d_in[11];
    const float* Wa  = (const float*)d_in[12];
    const float* ba  = (const float*)d_in[13];
    const float* Wc  = (const float*)d_in[14];
    const float* bc  = (const float*)d_in[15];
    float* out = (float*)d_out;

    convert_weights_kernel<<<(HDIM * HDIM + 255) / 256, 256>>>(W1a, W1b, W3a, W3b);
    prep_kernel<<<NPTS / 8, 256>>>(emb, dists, mask);
    // shift mlp_kernel to global launch index 5 so ncu (-s 5 -c 1) captures it
    noop_kernel<<<1, 32>>>();
    noop_kernel<<<1, 32>>>();
    noop_kernel<<<1, 32>>>();

    cudaFuncSetAttribute(mlp_kernel, cudaFuncAttributeMaxDynamicSharedMemorySize,
                         SMEM_BYTES);
    mlp_kernel<<<NPTS / MTILE, NTHREADS, SMEM_BYTES>>>(
        b1a, b1b, b3a, b3b, Wa, ba, Wc, bc, vdirs, out);
}